// round 4
// baseline (speedup 1.0000x reference)
#include <cuda_runtime.h>

#define BB 128
#define TT 1024
#define CC 128
#define LL 128
#define SS 257
#define EPSF 1e-7f
#define NEGF -1e30f
#define LN2F 0.69314718055994530942f
#define KSTEP 8          // DP steps per phase (no cross-warp comm inside a phase)
#define STRIDE 48        // warp base stride = 64 - 2*KSTEP
#define RING 32          // raw/log prob rows (4 phases deep)
#define SPAN 304         // 5*STRIDE + 64
#define NTHR 192

__device__ __forceinline__ float ex2f(float x){ float y; asm("ex2.approx.ftz.f32 %0,%1;":"=f"(y):"f"(x)); return y; }
__device__ __forceinline__ float lg2f(float x){ float y; asm("lg2.approx.f32 %0,%1;":"=f"(y):"f"(x)); return y; }
__device__ __forceinline__ void cp16(void* s, const void* g){
    unsigned sa = (unsigned)__cvta_generic_to_shared(s);
    asm volatile("cp.async.cg.shared.global [%0],[%1],16;"::"r"(sa),"l"(g):"memory");
}
__device__ __forceinline__ void cpcommit(){ asm volatile("cp.async.commit_group;":::"memory"); }
template<int N> __device__ __forceinline__ void cpwait(){ asm volatile("cp.async.wait_group %0;"::"n"(N):"memory"); }

__device__ __forceinline__ void issue_group(int q, int Tin, const float* __restrict__ yp,
                                            float (*ring)[CC], int tid)
{
    // 8 rows x 32 chunks(16B) = 256 chunks over 192 threads
    for (int c = tid; c < KSTEP * 32; c += NTHR) {
        int r  = c >> 5, ch = c & 31;
        int rg = q * KSTEP + r;
        if (rg < Tin)
            cp16(&ring[rg & (RING - 1)][ch * 4], yp + (size_t)rg * CC + ch * 4);
    }
    cpcommit();
}

__global__ __launch_bounds__(NTHR, 1)
void ctc_loss_kernel(const int* __restrict__ y_true,
                     const float* __restrict__ y_pred,
                     const int* __restrict__ input_len,
                     const int* __restrict__ label_len,
                     float* __restrict__ out)
{
    __shared__ __align__(16) float ring[RING][CC];  // prob rows; converted to log2 in place
    __shared__ float sbuf[2][SPAN];                 // log2 alpha exchange (per-phase parity)

    const int b    = blockIdx.x;
    const int tid  = threadIdx.x;
    const int w    = tid >> 5;
    const int lane = tid & 31;

    int Tin = input_len[b];
    if (Tin > TT) Tin = TT;
    if (Tin < 0)  Tin = 0;

    const int base = w * STRIDE;
    const int s0   = base + 2 * lane;              // even state (blank) owned by lane
    const int li   = (base >> 1) + lane;           // label index of odd state s0+1
    const int liC  = (li < LL) ? li : (LL - 1);
    const int ext_odd = y_true[b * LL + liC];
    bool skipb = false;
    if (li >= 1 && li < LL && ext_odd != y_true[b * LL + li - 1]) skipb = true;
    const bool w0l0 = (tid == 0);

    const float* __restrict__ yp_b = y_pred + (size_t)b * TT * CC;

    // log2-domain alpha registers
    float aE = (s0 == 0) ? 0.0f : NEGF;
    float aO = NEGF;
    // Tin==0 fallback stash (final read = sbuf[(nph-1)&1] = sbuf[1] when nph==0)
    sbuf[1][s0] = aE; sbuf[1][s0 + 1] = aO;

    // prefetch phases 0..2
    issue_group(0, Tin, yp_b, ring, tid);
    issue_group(1, Tin, yp_b, ring, tid);
    issue_group(2, Tin, yp_b, ring, tid);

    cpwait<2>();
    __syncthreads();            // publish raw phase-0 rows
    // convert phase-0 rows to log2 in place
    for (int c = tid; c < KSTEP * CC; c += NTHR) {
        int t = c >> 7, i = c & (CC - 1);
        if (t < Tin) ring[t][i] = lg2f(ring[t][i] + EPSF);
    }
    __syncthreads();            // publish converted phase-0 rows

    const int nph = (Tin + KSTEP - 1) / KSTEP;

    for (int ph = 0; ph < nph; ph++) {
        const int t0   = ph * KSTEP;
        const int kmax = (Tin - t0 < KSTEP) ? (Tin - t0) : KSTEP;
        const bool last = (ph == nph - 1);

        #pragma unroll
        for (int k = 0; k < KSTEP; k++) {
            if (k >= kmax) break;
            const float* rg = ring[(t0 + k) & (RING - 1)];
            float lpB = rg[CC - 1];
            float lpO = rg[ext_odd];
            float pm1 = __shfl_up_sync(0xffffffffu, aO, 1);
            if (w0l0) pm1 = NEGF;                  // state -1 does not exist
            // even (blank): logadd2(aE, pm1) + lpB
            float m  = fmaxf(aE, pm1);
            float d  = fminf(aE, pm1) - m;          // <= 0
            float nE = lpB + m + lg2f(1.0f + ex2f(d));
            // odd: logadd3(aO, aE, skip ? pm1 : NEG) + lpO
            float p2 = skipb ? pm1 : NEGF;
            float m2 = fmaxf(fmaxf(aO, aE), p2);
            float s2 = ex2f(aO - m2) + ex2f(aE - m2) + ex2f(p2 - m2);
            float nO = lpO + m2 + lg2f(s2);
            aE = nE; aO = nO;
        }

        // publish: halo for next phase (lanes 24..31), or full valid span if last
        float* sb = sbuf[ph & 1];
        if (last) {
            if (w == 0 || lane >= kmax) { sb[s0] = aE; sb[s0 + 1] = aO; }
        } else if (lane >= 24) {
            sb[s0] = aE; sb[s0 + 1] = aO;
        }

        cpwait<1>();            // raw rows for phase ph+1 landed (own copies)
        __syncthreads();        // publish raw ph+1 rows + sbuf writes

        if (!last) {
            // convert phase ph+1 rows to log2 in place
            for (int c = tid; c < KSTEP * CC; c += NTHR) {
                int r = c >> 7, i = c & (CC - 1);
                int t = t0 + KSTEP + r;
                if (t < Tin) ring[t & (RING - 1)][i] = lg2f(ring[t & (RING - 1)][i] + EPSF);
            }
        }
        issue_group(ph + 3, Tin, yp_b, ring, tid);   // distinct ring slots, safe pre-barrier

        __syncthreads();        // publish converted ph+1 rows

        if (!last && w > 0 && lane < KSTEP) {
            aE = sb[s0];        // refresh left halo from neighbor warp
            aO = sb[s0 + 1];
        }
    }

    cpwait<0>();
    __syncthreads();

    if (tid == 0) {
        int lab = label_len[b];
        if (lab < 0)  lab = 0;
        if (lab > LL) lab = LL;
        const float* fin = sbuf[(nph - 1) & 1];
        float aL = fin[2 * lab];
        int ip = 2 * lab - 1; if (ip < 0) ip = 0;
        float aP = fin[ip];
        float mm = fmaxf(aL, aP);
        out[b] = -LN2F * (mm + lg2f(ex2f(aL - mm) + ex2f(aP - mm)));
    }
}

extern "C" void kernel_launch(void* const* d_in, const int* in_sizes, int n_in,
                              void* d_out, int out_size) {
    const int*   y_true    = nullptr;
    const float* y_pred    = nullptr;
    const int*   input_len = nullptr;
    const int*   label_len = nullptr;
    for (int i = 0; i < n_in; ++i) {
        if (in_sizes[i] == BB * TT * CC)      y_pred = (const float*)d_in[i];
        else if (in_sizes[i] == BB * LL)      y_true = (const int*)d_in[i];
        else if (in_sizes[i] == BB) {
            if (!input_len) input_len = (const int*)d_in[i];
            else            label_len = (const int*)d_in[i];
        }
    }
    ctc_loss_kernel<<<BB, NTHR>>>(y_true, y_pred, input_len, label_len, (float*)d_out);
}

// round 6
// speedup vs baseline: 2.0864x; 2.0864x over previous
#include <cuda_runtime.h>

#define BB 128
#define TT 1024
#define CC 128
#define LL 128
#define EPSF 1e-7f
#define NEGF -1e30f
#define LN2F 0.69314718055994530942f
#define KSTEP 8          // DP steps per phase
#define STRIDE 48        // warp base stride = 64 - 2*KSTEP
#define RING 32          // prob rows in cp.async ring (4 phases)
#define SPAN 304         // 5*STRIDE + 64
#define NTHR 192
#define NW 6
#define LIMAX 160

__device__ __forceinline__ float ex2f(float x){ float y; asm("ex2.approx.ftz.f32 %0,%1;":"=f"(y):"f"(x)); return y; }
__device__ __forceinline__ float lg2f(float x){ float y; asm("lg2.approx.f32 %0,%1;":"=f"(y):"f"(x)); return y; }
__device__ __forceinline__ void cp16(void* s, const void* g){
    unsigned sa = (unsigned)__cvta_generic_to_shared(s);
    asm volatile("cp.async.cg.shared.global [%0],[%1],16;"::"r"(sa),"l"(g):"memory");
}
__device__ __forceinline__ void cpcommit(){ asm volatile("cp.async.commit_group;":::"memory"); }
template<int N> __device__ __forceinline__ void cpwait(){ asm volatile("cp.async.wait_group %0;"::"n"(N):"memory"); }

// exact 2^d for d <= 0 (two-factor; flush below 2^-252)
__device__ __forceinline__ float pow2m(int d){
    if (d <= -252) return 0.0f;
    int d1 = d >> 1;
    int d2 = d - d1;
    return __int_as_float((127 + d1) << 23) * __int_as_float((127 + d2) << 23);
}

__device__ __forceinline__ void issue_group(int q, int Tin, const float* __restrict__ yp,
                                            float (*ring)[CC], int tid)
{
    for (int c = tid; c < KSTEP * 32; c += NTHR) {
        int r  = c >> 5, ch = c & 31;
        int rg = q * KSTEP + r;
        if (rg < Tin)
            cp16(&ring[rg & (RING - 1)][ch * 4], yp + (size_t)rg * CC + ch * 4);
    }
    cpcommit();
}

__global__ __launch_bounds__(NTHR, 1)
void ctc_loss_kernel(const int* __restrict__ y_true,
                     const float* __restrict__ y_pred,
                     const int* __restrict__ input_len,
                     const int* __restrict__ label_len,
                     float* __restrict__ out)
{
    __shared__ __align__(16) float ring[RING][CC];
    __shared__ float sbuf[2][SPAN];
    __shared__ int   sbE[2][LIMAX];

    const int b    = blockIdx.x;
    const int tid  = threadIdx.x;
    const int w    = tid >> 5;
    const int lane = tid & 31;

    int Tin = input_len[b];
    if (Tin > TT) Tin = TT;
    if (Tin < 0)  Tin = 0;

    const int base = w * STRIDE;
    const int s0   = base + 2 * lane;
    const int li   = (base >> 1) + lane;
    const int liC  = (li < LL) ? li : (LL - 1);
    const int ext_odd = y_true[b * LL + liC];
    float skipm = 0.0f;
    if (li >= 1 && li < LL && ext_odd != y_true[b * LL + li - 1]) skipm = 1.0f;
    const bool w0l0 = (tid == 0);

    const float* __restrict__ yp_b = y_pred + (size_t)b * TT * CC;

    float xE = (s0 == 0) ? 1.0f : 0.0f;
    float xO = 0.0f;
    int   Ei = 0;

    sbuf[1][s0] = (s0 == 0) ? 0.0f : NEGF;
    sbuf[1][s0 + 1] = NEGF;

    issue_group(0, Tin, yp_b, ring, tid);
    issue_group(1, Tin, yp_b, ring, tid);
    issue_group(2, Tin, yp_b, ring, tid);
    cpwait<2>();
    __syncthreads();

    const int nph = (Tin + KSTEP - 1) / KSTEP;

    for (int ph = 0; ph < nph; ph++) {
        const int t0   = ph * KSTEP;
        const int kmax = (Tin - t0 < KSTEP) ? (Tin - t0) : KSTEP;
        const bool lastp = (ph == nph - 1);

        #pragma unroll
        for (int k = 0; k < KSTEP; k++) {
            if (k >= kmax) break;
            const float* rp = ring[(t0 + k) & (RING - 1)];
            float pB  = rp[CC - 1] + EPSF;
            float pO  = rp[ext_odd] + EPSF;
            float pm1 = __shfl_up_sync(0xffffffffu, xO, 1);
            int   Ep  = __shfl_up_sync(0xffffffffu, Ei, 1);
            if (w0l0) pm1 = 0.0f;
            bool alive = (__float_as_int(fmaxf(xE, xO)) > 0);
            int En; float ss;
            if (alive) { En = (Ei > Ep) ? Ei : Ep; ss = pow2m(Ei - En); }
            else       { En = Ep; ss = 0.0f; }
            float sp  = pow2m(Ep - En);
            float xEs = xE * ss, xOs = xO * ss;
            float pm  = pm1 * sp;
            xE = pB * (xEs + pm);
            xO = pO * fmaf(skipm, pm, xOs + xEs);
            Ei = En;
            if ((k & 3) == 3) {
                int mb = __float_as_int(fmaxf(xE, xO));
                if (mb > 0) {
                    int e  = (mb >> 23) - 127;
                    float sc = __int_as_float((127 - e) << 23);
                    xE *= sc; xO *= sc; Ei += e;
                }
            }
        }

        float* sb = sbuf[ph & 1];
        int*   se = sbE[ph & 1];
        if (!lastp) {
            if (lane >= 24) { sb[s0] = xE; sb[s0 + 1] = xO; se[li] = Ei; }
        } else {
            float fE = (float)Ei;
            float lE = fmaxf(lg2f(xE) + fE, NEGF);
            float lO = fmaxf(lg2f(xO) + fE, NEGF);
            if (w == 0 || lane >= kmax) { sb[s0] = lE; sb[s0 + 1] = lO; }
        }

        cpwait<1>();
        __syncthreads();
        issue_group(ph + 3, Tin, yp_b, ring, tid);

        if (!lastp && w > 0 && lane < 8) {
            xE = sb[s0]; xO = sb[s0 + 1]; Ei = se[li];
        }
    }

    cpwait<0>();
    __syncthreads();

    if (tid == 0) {
        int lab = label_len[b];
        if (lab < 0)  lab = 0;
        if (lab > LL) lab = LL;
        const float* fin = sbuf[(nph - 1) & 1];
        float aL = fin[2 * lab];
        int ip = 2 * lab - 1; if (ip < 0) ip = 0;
        float aP = fin[ip];
        float mm = fmaxf(aL, aP);
        out[b] = -LN2F * (mm + lg2f(ex2f(aL - mm) + ex2f(aP - mm)));
    }
}

extern "C" void kernel_launch(void* const* d_in, const int* in_sizes, int n_in,
                              void* d_out, int out_size) {
    const int*   y_true    = nullptr;
    const float* y_pred    = nullptr;
    const int*   input_len = nullptr;
    const int*   label_len = nullptr;
    for (int i = 0; i < n_in; ++i) {
        if (in_sizes[i] == BB * TT * CC)      y_pred = (const float*)d_in[i];
        else if (in_sizes[i] == BB * LL)      y_true = (const int*)d_in[i];
        else if (in_sizes[i] == BB) {
            if (!input_len) input_len = (const int*)d_in[i];
            else            label_len = (const int*)d_in[i];
        }
    }
    ctc_loss_kernel<<<BB, NTHR>>>(y_true, y_pred, input_len, label_len, (float*)d_out);
}